// round 2
// baseline (speedup 1.0000x reference)
#include <cuda_runtime.h>
#include <math.h>
#include <stdint.h>

#define T      4096
#define H      1024
#define IDIM   512
#define E      64
#define TOPK   2
#define TM     16
#define PPOS   (T*TOPK + E*TM)          // 9216 padded positions
#define MAXTILES (T*TOPK/TM + E)        // 576 worst-case tiles

// -------- scratch (device globals; no allocation allowed) --------
__device__ int   g_counts[E];
__device__ int   g_off[E+1];
__device__ int   g_tile_off[E+1];
__device__ int   g_cursor[E];
__device__ int   g_perm[PPOS];
__device__ float g_pw[PPOS];
__device__ int   g_sel[T*TOPK];
__device__ float g_w[T*TOPK];

// ---------------- init: zero out, counts, perm ----------------
__global__ void k_init(float* __restrict__ out) {
    int idx = blockIdx.x * blockDim.x + threadIdx.x;
    int stride = gridDim.x * blockDim.x;
    for (int i = idx; i < T * H; i += stride) out[i] = 0.f;
    if (idx < E) g_counts[idx] = 0;
    for (int i = idx; i < PPOS; i += stride) g_perm[i] = -1;
}

// ---------------- router: logits -> top2 -> weights ----------------
__global__ void __launch_bounds__(256) k_router(const float* __restrict__ x,
                                                const float* __restrict__ gw,
                                                const float* __restrict__ gb) {
    __shared__ float xs[H];
    __shared__ float red[256];
    __shared__ float logits[E];
    const int t = blockIdx.x;
    const int tid = threadIdx.x;

    const float4* xp4 = (const float4*)(x + (size_t)t * H);
    float4* xs4 = (float4*)xs;
    for (int i = tid; i < H / 4; i += 256) xs4[i] = xp4[i];
    __syncthreads();

    // 256 threads = 64 experts x 4 chunks of 256 H-elements
    const int e = tid & 63;
    const int chunk = tid >> 6;
    const float4* gwp = (const float4*)(gw + (size_t)e * H + chunk * 256);
    const float4* xc = (const float4*)(xs + chunk * 256);
    float acc = 0.f;
#pragma unroll 4
    for (int j = 0; j < 64; j++) {
        float4 wv = gwp[j];
        float4 xv = xc[j];
        acc += xv.x * wv.x + xv.y * wv.y + xv.z * wv.z + xv.w * wv.w;
    }
    red[tid] = acc;
    __syncthreads();
    if (tid < E)
        logits[tid] = red[tid] + red[tid + 64] + red[tid + 128] + red[tid + 192] + gb[tid];
    __syncthreads();

    if (tid == 0) {
        float l0 = -1e30f, l1 = -1e30f;
        int e0 = 0, e1 = 0;
        for (int k = 0; k < E; k++) {
            float l = logits[k];
            if (l > l0)      { l1 = l0; e1 = e0; l0 = l; e0 = k; }
            else if (l > l1) { l1 = l;  e1 = k; }
        }
        // renormalized top-2 softmax weights == 2-way softmax over (l0,l1)
        float r  = expf(l1 - l0);
        float w0 = 1.f / (1.f + r);
        float w1 = r * w0;
        g_sel[2 * t] = e0;  g_sel[2 * t + 1] = e1;
        g_w[2 * t]   = w0;  g_w[2 * t + 1]   = w1;
        atomicAdd(&g_counts[e0], 1);
        atomicAdd(&g_counts[e1], 1);
    }
}

// ---------------- scan: padded offsets + tile offsets ----------------
__global__ void k_scan() {
    if (blockIdx.x == 0 && threadIdx.x == 0) {
        int off = 0, toff = 0;
        for (int e = 0; e < E; e++) {
            g_off[e] = off;
            g_tile_off[e] = toff;
            g_cursor[e] = off;
            int tiles = (g_counts[e] + TM - 1) / TM;
            off += tiles * TM;
            toff += tiles;
        }
        g_off[E] = off;
        g_tile_off[E] = toff;
    }
}

// ---------------- scatter: fill per-expert token lists ----------------
__global__ void k_scatter() {
    int idx = blockIdx.x * blockDim.x + threadIdx.x;
    if (idx >= T * TOPK) return;
    int e = g_sel[idx];
    int pos = atomicAdd(&g_cursor[e], 1);
    g_perm[pos] = idx >> 1;
    g_pw[pos] = g_w[idx];
}

// ---------------- grouped expert FFN ----------------
// one block = one expert x 16-token tile. smem: xs[16][1024] + as[16][512]
__global__ void __launch_bounds__(256, 2) k_ffn(const float* __restrict__ x,
                                                const float* __restrict__ W1,
                                                const float* __restrict__ W2,
                                                const float* __restrict__ W3,
                                                float* __restrict__ out) {
    const int tile = blockIdx.x;
    if (tile >= g_tile_off[E]) return;

    // binary search for expert owning this tile
    int lo = 0, hi = E;
    while (lo + 1 < hi) {
        int mid = (lo + hi) >> 1;
        if (g_tile_off[mid] <= tile) lo = mid; else hi = mid;
    }
    const int e = lo;
    const int p0 = g_off[e] + (tile - g_tile_off[e]) * TM;

    __shared__ int   s_tok[TM];
    __shared__ float s_w[TM];
    extern __shared__ float smem[];
    float* xs = smem;               // TM * H floats
    float* as = smem + TM * H;      // TM * IDIM floats
    float4* xs4 = (float4*)xs;
    float4* as4 = (float4*)as;

    const int tid = threadIdx.x;
    if (tid < TM) {
        int tok = g_perm[p0 + tid];
        s_tok[tid] = tok;
        s_w[tid] = (tok >= 0) ? g_pw[p0 + tid] : 0.f;
    }
    __syncthreads();

    // load x tile (zeros for padded rows)
    for (int idx4 = tid; idx4 < TM * (H / 4); idx4 += 256) {
        int r = idx4 / (H / 4);
        int h4 = idx4 % (H / 4);
        int tok = s_tok[r];
        float4 v = make_float4(0.f, 0.f, 0.f, 0.f);
        if (tok >= 0) v = ((const float4*)(x + (size_t)tok * H))[h4];
        xs4[idx4] = v;
    }
    __syncthreads();

    // phase 1: h1 = x W1^T, h3 = x W3^T, a = silu(h1)*h3*w
    for (int pass = 0; pass < 2; pass++) {
        const int i = tid + pass * 256;
        const float4* w1p = (const float4*)(W1 + ((size_t)e * IDIM + i) * H);
        const float4* w3p = (const float4*)(W3 + ((size_t)e * IDIM + i) * H);
        float acc1[TM], acc3[TM];
#pragma unroll
        for (int r = 0; r < TM; r++) { acc1[r] = 0.f; acc3[r] = 0.f; }
        for (int h4 = 0; h4 < H / 4; h4++) {
            float4 w1v = w1p[h4];
            float4 w3v = w3p[h4];
#pragma unroll
            for (int r = 0; r < TM; r++) {
                float4 xv = xs4[r * (H / 4) + h4];
                acc1[r] += xv.x * w1v.x + xv.y * w1v.y + xv.z * w1v.z + xv.w * w1v.w;
                acc3[r] += xv.x * w3v.x + xv.y * w3v.y + xv.z * w3v.z + xv.w * w3v.w;
            }
        }
#pragma unroll
        for (int r = 0; r < TM; r++) {
            float h1 = acc1[r];
            float sig = 1.f / (1.f + expf(-h1));
            as[r * IDIM + i] = h1 * sig * acc3[r] * s_w[r];
        }
    }
    __syncthreads();

    // phase 2: y = a W2^T, scatter-add into out
    for (int pass = 0; pass < 4; pass++) {
        const int h = tid + pass * 256;
        const float4* w2p = (const float4*)(W2 + ((size_t)e * H + h) * IDIM);
        float acc[TM];
#pragma unroll
        for (int r = 0; r < TM; r++) acc[r] = 0.f;
        for (int i4 = 0; i4 < IDIM / 4; i4++) {
            float4 wv = w2p[i4];
#pragma unroll
            for (int r = 0; r < TM; r++) {
                float4 av = as4[r * (IDIM / 4) + i4];
                acc[r] += av.x * wv.x + av.y * wv.y + av.z * wv.z + av.w * wv.w;
            }
        }
#pragma unroll
        for (int r = 0; r < TM; r++) {
            int tok = s_tok[r];
            if (tok >= 0) atomicAdd(out + (size_t)tok * H + h, acc[r]);
        }
    }
}

// ---------------- launch ----------------
extern "C" void kernel_launch(void* const* d_in, const int* in_sizes, int n_in,
                              void* d_out, int out_size) {
    const float* x  = (const float*)d_in[0];
    const float* gw = (const float*)d_in[1];
    const float* gb = (const float*)d_in[2];
    const float* W1 = (const float*)d_in[3];
    const float* W2 = (const float*)d_in[4];
    const float* W3 = (const float*)d_in[5];
    float* out = (float*)d_out;

    const int ffn_smem = (TM * H + TM * IDIM) * (int)sizeof(float);  // 96 KB
    cudaFuncSetAttribute(k_ffn, cudaFuncAttributeMaxDynamicSharedMemorySize, ffn_smem);

    k_init<<<512, 256>>>(out);
    k_router<<<T, 256>>>(x, gw, gb);
    k_scan<<<1, 32>>>();
    k_scatter<<<(T * TOPK + 255) / 256, 256>>>();
    k_ffn<<<MAXTILES, 256, ffn_smem>>>(x, W1, W2, W3, out);
}

// round 4
// speedup vs baseline: 1.2861x; 1.2861x over previous
#include <cuda_runtime.h>
#include <math.h>
#include <stdint.h>

#define T      4096
#define H      1024
#define IDIM   512
#define E      64
#define TOPK   2
#define TMTOK  128
#define NTILES 128
#define PPOS   (T*TOPK + E*TMTOK)

// ---------------- device scratch ----------------
__device__ int   g_counts[E];
__device__ int   g_off[E+1];
__device__ int   g_tile_off[E+1];
__device__ int   g_cursor[E];
__device__ int   g_perm[PPOS];
__device__ float g_pw[PPOS];
__device__ int   g_sel[T*TOPK];
__device__ float g_w[T*TOPK];
__device__ int   g_ypos[T*TOPK];
__device__ uint2 g_xhi[(T+1)*H/4],   g_xlo[(T+1)*H/4];
__device__ uint2 g_w1hi[E*IDIM*H/4], g_w1lo[E*IDIM*H/4];
__device__ uint2 g_w3hi[E*IDIM*H/4], g_w3lo[E*IDIM*H/4];
__device__ uint2 g_w2hi[E*H*IDIM/4], g_w2lo[E*H*IDIM/4];
__device__ uint32_t g_ahi32[NTILES*TMTOK*IDIM/2], g_alo32[NTILES*TMTOK*IDIM/2];
__device__ float g_y[(size_t)NTILES*TMTOK*H];

// ---------------- helpers ----------------
__device__ __forceinline__ uint32_t smem_u32(const void* p) {
    uint32_t a;
    asm("{ .reg .u64 t; cvta.to.shared.u64 t, %1; cvt.u32.u64 %0, t; }" : "=r"(a) : "l"(p));
    return a;
}
__device__ __forceinline__ void cpa16(uint32_t dst, const void* src) {
    asm volatile("cp.async.cg.shared.global [%0], [%1], 16;" :: "r"(dst), "l"(src) : "memory");
}
#define CP_COMMIT() asm volatile("cp.async.commit_group;" ::: "memory")
#define CP_WAIT(n)  asm volatile("cp.async.wait_group %0;" :: "n"(n) : "memory")

__device__ __forceinline__ void ldm4(uint32_t* r, uint32_t addr) {
    asm volatile("ldmatrix.sync.aligned.m8n8.x4.shared.b16 {%0,%1,%2,%3}, [%4];"
        : "=r"(r[0]), "=r"(r[1]), "=r"(r[2]), "=r"(r[3]) : "r"(addr));
}
__device__ __forceinline__ void mma16(float* d, const uint32_t* a, uint32_t b0, uint32_t b1) {
    asm volatile("mma.sync.aligned.m16n8k16.row.col.f32.bf16.bf16.f32 "
        "{%0,%1,%2,%3}, {%4,%5,%6,%7}, {%8,%9}, {%0,%1,%2,%3};"
        : "+f"(d[0]), "+f"(d[1]), "+f"(d[2]), "+f"(d[3])
        : "r"(a[0]), "r"(a[1]), "r"(a[2]), "r"(a[3]), "r"(b0), "r"(b1));
}
__device__ __forceinline__ void split2(float a, float b, uint32_t& hi, uint32_t& lo) {
    uint32_t h;
    asm("cvt.rn.bf16x2.f32 %0, %1, %2;" : "=r"(h) : "f"(b), "f"(a));
    float ra = a - __uint_as_float(h << 16);
    float rb = b - __uint_as_float(h & 0xffff0000u);
    asm("cvt.rn.bf16x2.f32 %0, %1, %2;" : "=r"(lo) : "f"(rb), "f"(ra));
    hi = h;
}

// ---------------- convert fp32 -> bf16 hi/lo ----------------
#define X4   (T*H/4)
#define W14  (E*IDIM*H/4)
#define TOT4 (X4 + 3*W14)
__global__ void k_cvt(const float* __restrict__ x, const float* __restrict__ W1,
                      const float* __restrict__ W2, const float* __restrict__ W3) {
    size_t gid = (size_t)blockIdx.x * blockDim.x + threadIdx.x;
    size_t stride = (size_t)gridDim.x * blockDim.x;
    if (gid < H/4) { g_xhi[(size_t)T*H/4 + gid] = make_uint2(0,0); g_xlo[(size_t)T*H/4 + gid] = make_uint2(0,0); }
    for (size_t i = gid; i < TOT4; i += stride) {
        const float4* s; uint2 *dh, *dl; size_t j = i;
        if (j < X4)            { s = (const float4*)x;  dh = g_xhi;  dl = g_xlo; }
        else { j -= X4;
            if (j < W14)       { s = (const float4*)W1; dh = g_w1hi; dl = g_w1lo; }
            else { j -= W14;
                if (j < W14)   { s = (const float4*)W3; dh = g_w3hi; dl = g_w3lo; }
                else { j -= W14; s = (const float4*)W2; dh = g_w2hi; dl = g_w2lo; } } }
        float4 v = s[j];
        uint32_t h0,l0,h1,l1;
        split2(v.x, v.y, h0, l0);
        split2(v.z, v.w, h1, l1);
        dh[j] = make_uint2(h0, h1);
        dl[j] = make_uint2(l0, l1);
    }
}

// ---------------- init ----------------
__global__ void k_init() {
    int idx = blockIdx.x * blockDim.x + threadIdx.x;
    int stride = gridDim.x * blockDim.x;
    if (idx < E) g_counts[idx] = 0;
    for (int i = idx; i < PPOS; i += stride) g_perm[i] = -1;
}

// ---------------- router (16 tokens / block) ----------------
__global__ void __launch_bounds__(256) k_router(const float* __restrict__ x,
                                                const float* __restrict__ gw,
                                                const float* __restrict__ gb) {
    extern __shared__ float rsm[];
    float* xs  = rsm;
    float* red = rsm + 16384;
    float* lg  = red + 4096;
    const int t0 = blockIdx.x * 16;
    const int tid = threadIdx.x;
    float4* xs4 = (float4*)xs;
    const float4* xg = (const float4*)(x + (size_t)t0 * H);
    for (int i = tid; i < 16 * H / 4; i += 256) xs4[i] = xg[i];
    __syncthreads();
    const int e = tid & 63, ck = tid >> 6;
    const float4* gwp = (const float4*)(gw + (size_t)e * H + ck * 256);
    float acc[16];
#pragma unroll
    for (int r = 0; r < 16; r++) acc[r] = 0.f;
    for (int j = 0; j < 64; j++) {
        float4 wv = gwp[j];
#pragma unroll
        for (int r = 0; r < 16; r++) {
            float4 xv = xs4[r * 256 + ck * 64 + j];
            acc[r] += xv.x * wv.x + xv.y * wv.y + xv.z * wv.z + xv.w * wv.w;
        }
    }
#pragma unroll
    for (int r = 0; r < 16; r++) red[tid * 16 + r] = acc[r];
    __syncthreads();
    if (tid < 64) {
#pragma unroll
        for (int r = 0; r < 16; r++)
            lg[r * 64 + tid] = red[tid * 16 + r] + red[(tid + 64) * 16 + r] +
                               red[(tid + 128) * 16 + r] + red[(tid + 192) * 16 + r] + gb[tid];
    }
    __syncthreads();
    if (tid < 16) {
        int t = t0 + tid;
        float l0 = -1e30f, l1 = -1e30f;
        int e0 = 0, e1 = 0;
        for (int k = 0; k < E; k++) {
            float l = lg[tid * 64 + k];
            if (l > l0)      { l1 = l0; e1 = e0; l0 = l; e0 = k; }
            else if (l > l1) { l1 = l;  e1 = k; }
        }
        float rr = expf(l1 - l0);
        float w0 = 1.f / (1.f + rr);
        float w1 = rr * w0;
        g_sel[2 * t] = e0;  g_sel[2 * t + 1] = e1;
        g_w[2 * t]   = w0;  g_w[2 * t + 1]   = w1;
        atomicAdd(&g_counts[e0], 1);
        atomicAdd(&g_counts[e1], 1);
    }
}

// ---------------- scan + scatter ----------------
__global__ void k_scan() {
    if (threadIdx.x == 0 && blockIdx.x == 0) {
        int off = 0, toff = 0;
        for (int e = 0; e < E; e++) {
            g_off[e] = off; g_tile_off[e] = toff; g_cursor[e] = off;
            int tiles = (g_counts[e] + TMTOK - 1) / TMTOK;
            off += tiles * TMTOK; toff += tiles;
        }
        g_off[E] = off; g_tile_off[E] = toff;
    }
}
__global__ void k_scatter() {
    int idx = blockIdx.x * blockDim.x + threadIdx.x;
    if (idx >= T * TOPK) return;
    int e = g_sel[idx];
    int pos = atomicAdd(&g_cursor[e], 1);
    g_perm[pos] = idx >> 1;
    g_pw[pos] = g_w[idx];
    int local = pos - g_off[e];
    g_ypos[idx] = (g_tile_off[e] + (local >> 7)) * TMTOK + (local & 127);
}

// ---------------- FFN: mma.sync bf16x3 ----------------
#define KC      32
#define RSTRIDE 80
#define STAGE   (512*RSTRIDE)
#define SMEM_REQ (2*STAGE)

// ldmatrix tile address: 16 rows starting at rowbase, k-sub ks (16 elems)
__device__ __forceinline__ uint32_t adr(uint32_t buf, int rowbase, int ks, int lane) {
    return buf + (uint32_t)(rowbase + (lane & 15)) * RSTRIDE + (uint32_t)(ks * 2 + (lane >> 4)) * 16;
}

__device__ __forceinline__ void ld_g1(uint32_t buf, const int* s_tok, int e, int ic, int k) {
    const int tid = threadIdx.x;
#pragma unroll
    for (int j = 0; j < 2; j++) {
        int row = tid + j * 256;
        const char* src;
        if (row < 256) {
            int tok = s_tok[row & 127];
            if (tok < 0) tok = T;
            const char* base = (row < 128) ? (const char*)g_xhi : (const char*)g_xlo;
            src = base + (size_t)tok * (H * 2) + k * (KC * 2);
        } else {
            int n = row & 63;
            int sel = (row - 256) >> 6;
            const char* base = (sel == 0) ? (const char*)g_w1hi :
                               (sel == 1) ? (const char*)g_w1lo :
                               (sel == 2) ? (const char*)g_w3hi : (const char*)g_w3lo;
            src = base + ((size_t)(e * IDIM + ic * 64 + n)) * (H * 2) + k * (KC * 2);
        }
        uint32_t d = buf + (uint32_t)row * RSTRIDE;
        cpa16(d, src); cpa16(d + 16, src + 16); cpa16(d + 32, src + 32); cpa16(d + 48, src + 48);
    }
}
__device__ __forceinline__ void ld_g2(uint32_t buf, int tile, int e, int hc, int k) {
    const int tid = threadIdx.x;
#pragma unroll
    for (int j = 0; j < 2; j++) {
        int row = tid + j * 256;
        if (row >= 384) break;
        const char* src;
        if (row < 256) {
            const char* base = (row < 128) ? (const char*)g_ahi32 : (const char*)g_alo32;
            src = base + ((size_t)tile * TMTOK + (row & 127)) * (IDIM * 2) + k * (KC * 2);
        } else {
            int n = row & 63;
            const char* base = (row < 320) ? (const char*)g_w2hi : (const char*)g_w2lo;
            src = base + ((size_t)(e * H + hc * 64 + n)) * (IDIM * 2) + k * (KC * 2);
        }
        uint32_t d = buf + (uint32_t)row * RSTRIDE;
        cpa16(d, src); cpa16(d + 16, src + 16); cpa16(d + 32, src + 32); cpa16(d + 48, src + 48);
    }
}

__global__ void __launch_bounds__(256, 1) k_ffn() {
    const int tile = blockIdx.x;
    if (tile >= g_tile_off[E]) return;
    extern __shared__ char sm[];
    const uint32_t sb = smem_u32(sm);
    __shared__ int   s_tok[TMTOK];
    __shared__ float s_w[TMTOK];

    const int tid = threadIdx.x, lane = tid & 31, wid = tid >> 5;
    const int wm = wid & 3, wn = wid >> 2;

    int lo = 0, hi = E;
    while (lo + 1 < hi) { int m = (lo + hi) >> 1; if (g_tile_off[m] <= tile) lo = m; else hi = m; }
    const int e = lo;
    const int p0 = g_off[e] + (tile - g_tile_off[e]) * TMTOK;

    if (tid < TMTOK) {
        int tk = g_perm[p0 + tid];
        s_tok[tid] = tk;
        s_w[tid] = (tk >= 0) ? g_pw[p0 + tid] : 0.f;
    }
    __syncthreads();

    const uint32_t bufs[2] = { sb, sb + STAGE };
    const int rbase = wm * 32 + (lane >> 2);

    // ================= GEMM1: h1/h3, 8 I-chunks of 64 =================
    for (int ic = 0; ic < 8; ic++) {
        ld_g1(bufs[0], s_tok, e, ic, 0); CP_COMMIT();
        float c1[2][4][4], c3[2][4][4];
#pragma unroll
        for (int a = 0; a < 2; a++)
#pragma unroll
            for (int b = 0; b < 4; b++)
#pragma unroll
                for (int c = 0; c < 4; c++) { c1[a][b][c] = 0.f; c3[a][b][c] = 0.f; }

        for (int k = 0; k < 32; k++) {
            if (k + 1 < 32) { ld_g1(bufs[(k + 1) & 1], s_tok, e, ic, k + 1); CP_COMMIT(); CP_WAIT(1); }
            else            { CP_WAIT(0); }
            __syncthreads();
            uint32_t cb = bufs[k & 1];
#pragma unroll
            for (int ks = 0; ks < 2; ks++) {
                uint32_t ah[2][4], al[2][4];
#pragma unroll
                for (int mi = 0; mi < 2; mi++) {
                    ldm4(ah[mi], adr(cb, wm * 32 + mi * 16, ks, lane));
                    ldm4(al[mi], adr(cb, 128 + wm * 32 + mi * 16, ks, lane));
                }
#pragma unroll
                for (int nj = 0; nj < 2; nj++) {
                    uint32_t b1h[4], b1l[4], b3h[4], b3l[4];
                    ldm4(b1h, adr(cb, 256 + wn * 32 + nj * 16, ks, lane));
                    ldm4(b1l, adr(cb, 320 + wn * 32 + nj * 16, ks, lane));
                    ldm4(b3h, adr(cb, 384 + wn * 32 + nj * 16, ks, lane));
                    ldm4(b3l, adr(cb, 448 + wn * 32 + nj * 16, ks, lane));
#pragma unroll
                    for (int nk = 0; nk < 2; nk++) {
                        int n4 = nj * 2 + nk;
#pragma unroll
                        for (int mi = 0; mi < 2; mi++) {
                            mma16(c1[mi][n4], ah[mi], b1h[nk], b1h[nk + 2]);
                            mma16(c1[mi][n4], al[mi], b1h[nk], b1h[nk + 2]);
                            mma16(c1[mi][n4], ah[mi], b1l[nk], b1l[nk + 2]);
                            mma16(c3[mi][n4], ah[mi], b3h[nk], b3h[nk + 2]);
                            mma16(c3[mi][n4], al[mi], b3h[nk], b3h[nk + 2]);
                            mma16(c3[mi][n4], ah[mi], b3l[nk], b3l[nk + 2]);
                        }
                    }
                }
            }
            __syncthreads();
        }
        // epilogue: silu(h1)*h3*w -> bf16 hi/lo scratch
        const int cbase = ic * 64 + wn * 32 + ((lane & 3) << 1);
#pragma unroll
        for (int mi = 0; mi < 2; mi++)
#pragma unroll
            for (int n4 = 0; n4 < 4; n4++)
#pragma unroll
                for (int hf = 0; hf < 2; hf++) {
                    int row = rbase + mi * 16 + hf * 8;
                    int col = cbase + n4 * 8;
                    float w = s_w[row];
                    float h1a = c1[mi][n4][hf * 2], h1b = c1[mi][n4][hf * 2 + 1];
                    float a0 = h1a / (1.f + __expf(-h1a)) * c3[mi][n4][hf * 2] * w;
                    float a1 = h1b / (1.f + __expf(-h1b)) * c3[mi][n4][hf * 2 + 1] * w;
                    uint32_t hv, lv; split2(a0, a1, hv, lv);
                    size_t o = ((size_t)(tile * TMTOK + row) * IDIM + col) >> 1;
                    g_ahi32[o] = hv; g_alo32[o] = lv;
                }
        __syncthreads();
    }
    __threadfence();
    __syncthreads();

    // ================= GEMM2: y = a @ W2^T, 16 H-chunks of 64 =================
    for (int hc = 0; hc < 16; hc++) {
        ld_g2(bufs[0], tile, e, hc, 0); CP_COMMIT();
        float cc[2][4][4];
#pragma unroll
        for (int a = 0; a < 2; a++)
#pragma unroll
            for (int b = 0; b < 4; b++)
#pragma unroll
                for (int c = 0; c < 4; c++) cc[a][b][c] = 0.f;

        for (int k = 0; k < 16; k++) {
            if (k + 1 < 16) { ld_g2(bufs[(k + 1) & 1], tile, e, hc, k + 1); CP_COMMIT(); CP_WAIT(1); }
            else            { CP_WAIT(0); }
            __syncthreads();
            uint32_t cb = bufs[k & 1];
#pragma unroll
            for (int ks = 0; ks < 2; ks++) {
                uint32_t ah[2][4], al[2][4];
#pragma unroll
                for (int mi = 0; mi < 2; mi++) {
                    ldm4(ah[mi], adr(cb, wm * 32 + mi * 16, ks, lane));
                    ldm4(al[mi], adr(cb, 128 + wm * 32 + mi * 16, ks, lane));
                }
#pragma unroll
                for (int nj = 0; nj < 2; nj++) {
                    uint32_t b2h[4], b2l[4];
                    ldm4(b2h, adr(cb, 256 + wn * 32 + nj * 16, ks, lane));
                    ldm4(b2l, adr(cb, 320 + wn * 32 + nj * 16, ks, lane));
#pragma unroll
                    for (int nk = 0; nk < 2; nk++) {
                        int n4 = nj * 2 + nk;
#pragma unroll
                        for (int mi = 0; mi < 2; mi++) {
                            mma16(cc[mi][n4], ah[mi], b2h[nk], b2h[nk + 2]);
                            mma16(cc[mi][n4], al[mi], b2h[nk], b2h[nk + 2]);
                            mma16(cc[mi][n4], ah[mi], b2l[nk], b2l[nk + 2]);
                        }
                    }
                }
            }
            __syncthreads();
        }
        // epilogue: write fp32 y
#pragma unroll
        for (int mi = 0; mi < 2; mi++)
#pragma unroll
            for (int n4 = 0; n4 < 4; n4++)
#pragma unroll
                for (int hf = 0; hf < 2; hf++) {
                    int row = rbase + mi * 16 + hf * 8;
                    int col = hc * 64 + wn * 32 + n4 * 8 + ((lane & 3) << 1);
                    float2 v = make_float2(cc[mi][n4][hf * 2], cc[mi][n4][hf * 2 + 1]);
                    *(float2*)&g_y[(size_t)(tile * TMTOK + row) * H + col] = v;
                }
        __syncthreads();
    }
}

// ---------------- gather ----------------
__global__ void k_gather(float* __restrict__ out) {
    int idx = blockIdx.x * 256 + threadIdx.x;
    if (idx >= T * H / 4) return;
    int t = idx / (H / 4), c = idx % (H / 4);
    int p0 = g_ypos[2 * t], p1 = g_ypos[2 * t + 1];
    float4 a = ((const float4*)g_y)[(size_t)p0 * (H / 4) + c];
    float4 b = ((const float4*)g_y)[(size_t)p1 * (H / 4) + c];
    ((float4*)out)[idx] = make_float4(a.x + b.x, a.y + b.y, a.z + b.z, a.w + b.w);
}

// ---------------- launch ----------------
extern "C" void kernel_launch(void* const* d_in, const int* in_sizes, int n_in,
                              void* d_out, int out_size) {
    const float* x  = (const float*)d_in[0];
    const float* gw = (const float*)d_in[1];
    const float* gb = (const float*)d_in[2];
    const float* W1 = (const float*)d_in[3];
    const float* W2 = (const float*)d_in[4];
    const float* W3 = (const float*)d_in[5];
    float* out = (float*)d_out;

    cudaFuncSetAttribute(k_router, cudaFuncAttributeMaxDynamicSharedMemorySize, 86016);
    cudaFuncSetAttribute(k_ffn,    cudaFuncAttributeMaxDynamicSharedMemorySize, SMEM_REQ);

    k_cvt<<<2048, 256>>>(x, W1, W2, W3);
    k_init<<<64, 256>>>();
    k_router<<<T / 16, 256, 86016>>>(x, gw, gb);
    k_scan<<<1, 32>>>();
    k_scatter<<<(T * TOPK + 255) / 256, 256>>>();
    k_ffn<<<NTILES, 256, SMEM_REQ>>>();
    k_gather<<<(T * H / 4 + 255) / 256, 256>>>(out);
}

// round 5
// speedup vs baseline: 1.3640x; 1.0606x over previous
#include <cuda_runtime.h>
#include <math.h>
#include <stdint.h>

#define T      4096
#define H      1024
#define IDIM   512
#define E      64
#define TOPK   2
#define TMTOK  128
#define NTILES 128
#define PPOS   (T*TOPK + E*TMTOK)

// ---------------- device scratch ----------------
__device__ int   g_off[E+1];
__device__ int   g_tile_off[E+1];
__device__ int   g_perm[PPOS];
__device__ float g_pw[PPOS];
__device__ int   g_sel[T*TOPK];
__device__ float g_w[T*TOPK];
__device__ int   g_ypos[T*TOPK];
__device__ uint2 g_xhi[(T+1)*H/4],   g_xlo[(T+1)*H/4];
__device__ uint2 g_w1hi[E*IDIM*H/4], g_w1lo[E*IDIM*H/4];
__device__ uint2 g_w3hi[E*IDIM*H/4], g_w3lo[E*IDIM*H/4];
__device__ uint2 g_w2hi[E*H*IDIM/4], g_w2lo[E*H*IDIM/4];
__device__ uint32_t g_ahi32[NTILES*TMTOK*IDIM/2], g_alo32[NTILES*TMTOK*IDIM/2];
__device__ float g_y[(size_t)NTILES*TMTOK*H];

// ---------------- helpers ----------------
__device__ __forceinline__ uint32_t smem_u32(const void* p) {
    uint32_t a;
    asm("{ .reg .u64 t; cvta.to.shared.u64 t, %1; cvt.u32.u64 %0, t; }" : "=r"(a) : "l"(p));
    return a;
}
__device__ __forceinline__ void cpa16(uint32_t dst, const void* src) {
    asm volatile("cp.async.cg.shared.global [%0], [%1], 16;" :: "r"(dst), "l"(src) : "memory");
}
#define CP_COMMIT() asm volatile("cp.async.commit_group;" ::: "memory")
#define CP_WAIT(n)  asm volatile("cp.async.wait_group %0;" :: "n"(n) : "memory")

__device__ __forceinline__ void ldm4(uint32_t* r, uint32_t addr) {
    asm volatile("ldmatrix.sync.aligned.m8n8.x4.shared.b16 {%0,%1,%2,%3}, [%4];"
        : "=r"(r[0]), "=r"(r[1]), "=r"(r[2]), "=r"(r[3]) : "r"(addr));
}
__device__ __forceinline__ void mma16(float* d, const uint32_t* a, uint32_t b0, uint32_t b1) {
    asm volatile("mma.sync.aligned.m16n8k16.row.col.f32.bf16.bf16.f32 "
        "{%0,%1,%2,%3}, {%4,%5,%6,%7}, {%8,%9}, {%0,%1,%2,%3};"
        : "+f"(d[0]), "+f"(d[1]), "+f"(d[2]), "+f"(d[3])
        : "r"(a[0]), "r"(a[1]), "r"(a[2]), "r"(a[3]), "r"(b0), "r"(b1));
}
__device__ __forceinline__ void split2(float a, float b, uint32_t& hi, uint32_t& lo) {
    uint32_t h;
    asm("cvt.rn.bf16x2.f32 %0, %1, %2;" : "=r"(h) : "f"(b), "f"(a));
    float ra = a - __uint_as_float(h << 16);
    float rb = b - __uint_as_float(h & 0xffff0000u);
    asm("cvt.rn.bf16x2.f32 %0, %1, %2;" : "=r"(lo) : "f"(rb), "f"(ra));
    hi = h;
}

// ---------------- convert fp32 -> bf16 hi/lo ----------------
#define X4   (T*H/4)
#define W14  (E*IDIM*H/4)
#define TOT4 (X4 + 3*W14)
__global__ void k_cvt(const float* __restrict__ x, const float* __restrict__ W1,
                      const float* __restrict__ W2, const float* __restrict__ W3) {
    size_t gid = (size_t)blockIdx.x * blockDim.x + threadIdx.x;
    size_t stride = (size_t)gridDim.x * blockDim.x;
    if (gid < H/4) { g_xhi[(size_t)T*H/4 + gid] = make_uint2(0,0); g_xlo[(size_t)T*H/4 + gid] = make_uint2(0,0); }
    for (size_t i = gid; i < TOT4; i += stride) {
        const float4* s; uint2 *dh, *dl; size_t j = i;
        if (j < X4)            { s = (const float4*)x;  dh = g_xhi;  dl = g_xlo; }
        else { j -= X4;
            if (j < W14)       { s = (const float4*)W1; dh = g_w1hi; dl = g_w1lo; }
            else { j -= W14;
                if (j < W14)   { s = (const float4*)W3; dh = g_w3hi; dl = g_w3lo; }
                else { j -= W14; s = (const float4*)W2; dh = g_w2hi; dl = g_w2lo; } } }
        float4 v = s[j];
        uint32_t h0,l0,h1,l1;
        split2(v.x, v.y, h0, l0);
        split2(v.z, v.w, h1, l1);
        dh[j] = make_uint2(h0, h1);
        dl[j] = make_uint2(l0, l1);
    }
}

// ---------------- router (16 tokens / block) ----------------
__global__ void __launch_bounds__(256) k_router(const float* __restrict__ x,
                                                const float* __restrict__ gw,
                                                const float* __restrict__ gb) {
    extern __shared__ float rsm[];
    float* xs  = rsm;
    float* red = rsm + 16384;
    float* lg  = red + 4096;
    const int t0 = blockIdx.x * 16;
    const int tid = threadIdx.x;
    float4* xs4 = (float4*)xs;
    const float4* xg = (const float4*)(x + (size_t)t0 * H);
    for (int i = tid; i < 16 * H / 4; i += 256) xs4[i] = xg[i];
    __syncthreads();
    const int e = tid & 63, ck = tid >> 6;
    const float4* gwp = (const float4*)(gw + (size_t)e * H + ck * 256);
    float acc[16];
#pragma unroll
    for (int r = 0; r < 16; r++) acc[r] = 0.f;
    for (int j = 0; j < 64; j++) {
        float4 wv = gwp[j];
#pragma unroll
        for (int r = 0; r < 16; r++) {
            float4 xv = xs4[r * 256 + ck * 64 + j];
            acc[r] += xv.x * wv.x + xv.y * wv.y + xv.z * wv.z + xv.w * wv.w;
        }
    }
#pragma unroll
    for (int r = 0; r < 16; r++) red[tid * 16 + r] = acc[r];
    __syncthreads();
    if (tid < 64) {
#pragma unroll
        for (int r = 0; r < 16; r++)
            lg[r * 64 + tid] = red[tid * 16 + r] + red[(tid + 64) * 16 + r] +
                               red[(tid + 128) * 16 + r] + red[(tid + 192) * 16 + r] + gb[tid];
    }
    __syncthreads();
    if (tid < 16) {
        int t = t0 + tid;
        float l0 = -1e30f, l1 = -1e30f;
        int e0 = 0, e1 = 0;
        for (int k = 0; k < E; k++) {
            float l = lg[tid * 64 + k];
            if (l > l0)      { l1 = l0; e1 = e0; l0 = l; e0 = k; }
            else if (l > l1) { l1 = l;  e1 = k; }
        }
        float rr = expf(l1 - l0);
        float w0 = 1.f / (1.f + rr);
        float w1 = rr * w0;
        g_sel[2 * t] = e0;  g_sel[2 * t + 1] = e1;
        g_w[2 * t]   = w0;  g_w[2 * t + 1]   = w1;
    }
}

// ---------------- aux: histogram + scan + pad + scatter (one block) ----------------
__global__ void __launch_bounds__(256) k_aux() {
    __shared__ int hist[E];
    __shared__ int soff[E+1], stoff[E+1];
    __shared__ int cur[E];
    const int tid = threadIdx.x;
    if (tid < E) hist[tid] = 0;
    __syncthreads();
    for (int i = tid; i < T * TOPK; i += 256) atomicAdd(&hist[g_sel[i]], 1);
    __syncthreads();
    if (tid == 0) {
        int off = 0, toff = 0;
        for (int e = 0; e < E; e++) {
            soff[e] = off; stoff[e] = toff;
            int tiles = (hist[e] + TMTOK - 1) / TMTOK;
            off += tiles * TMTOK; toff += tiles;
        }
        soff[E] = off; stoff[E] = toff;
    }
    __syncthreads();
    if (tid < E) { cur[tid] = soff[tid]; g_off[tid] = soff[tid]; g_tile_off[tid] = stoff[tid]; }
    if (tid == 0) { g_off[E] = soff[E]; g_tile_off[E] = stoff[E]; }
    for (int i = tid; i < PPOS; i += 256) g_perm[i] = -1;
    __syncthreads();
    for (int i = tid; i < T * TOPK; i += 256) {
        int e = g_sel[i];
        int pos = atomicAdd(&cur[e], 1);
        g_perm[pos] = i >> 1;
        g_pw[pos] = g_w[i];
        int local = pos - soff[e];
        g_ypos[i] = (stoff[e] + (local >> 7)) * TMTOK + (local & 127);
    }
}

// ---------------- FFN: 16 warps, 3-stage cp.async ring ----------------
#define KC      32
#define RSTRIDE 80
#define STAGE   (512*RSTRIDE)
#define SMEM_REQ (3*STAGE)

__device__ __forceinline__ uint32_t adr(uint32_t buf, int rowbase, int ks, int lane) {
    return buf + (uint32_t)(rowbase + (lane & 15)) * RSTRIDE + (uint32_t)(ks * 2 + (lane >> 4)) * 16;
}

__device__ __forceinline__ void ld_g1(uint32_t buf, const int* s_tok, int e, int ic, int k) {
    const int row = threadIdx.x;   // 512 threads = 512 rows
    const char* src;
    if (row < 256) {
        int tok = s_tok[row & 127];
        if (tok < 0) tok = T;
        const char* base = (row < 128) ? (const char*)g_xhi : (const char*)g_xlo;
        src = base + (size_t)tok * (H * 2) + k * (KC * 2);
    } else {
        int n = row & 63;
        int sel = (row - 256) >> 6;
        const char* base = (sel == 0) ? (const char*)g_w1hi :
                           (sel == 1) ? (const char*)g_w1lo :
                           (sel == 2) ? (const char*)g_w3hi : (const char*)g_w3lo;
        src = base + ((size_t)(e * IDIM + ic * 64 + n)) * (H * 2) + k * (KC * 2);
    }
    uint32_t d = buf + (uint32_t)row * RSTRIDE;
    cpa16(d, src); cpa16(d + 16, src + 16); cpa16(d + 32, src + 32); cpa16(d + 48, src + 48);
}
__device__ __forceinline__ void ld_g2(uint32_t buf, int tile, int e, int hc, int k) {
    const int row = threadIdx.x;
    if (row >= 384) return;
    const char* src;
    if (row < 256) {
        const char* base = (row < 128) ? (const char*)g_ahi32 : (const char*)g_alo32;
        src = base + ((size_t)tile * TMTOK + (row & 127)) * (IDIM * 2) + k * (KC * 2);
    } else {
        int n = row & 63;
        const char* base = (row < 320) ? (const char*)g_w2hi : (const char*)g_w2lo;
        src = base + ((size_t)(e * H + hc * 64 + n)) * (IDIM * 2) + k * (KC * 2);
    }
    uint32_t d = buf + (uint32_t)row * RSTRIDE;
    cpa16(d, src); cpa16(d + 16, src + 16); cpa16(d + 32, src + 32); cpa16(d + 48, src + 48);
}

__global__ void __launch_bounds__(512, 1) k_ffn() {
    const int tile = blockIdx.x;
    if (tile >= g_tile_off[E]) return;
    extern __shared__ char sm[];
    const uint32_t sb = smem_u32(sm);
    __shared__ int   s_tok[TMTOK];
    __shared__ float s_w[TMTOK];

    const int tid = threadIdx.x, lane = tid & 31, wid = tid >> 5;
    const int wm = wid & 3, wn = wid >> 2;     // 4x4 warp grid: M32 x N16 per warp

    int lo = 0, hi = E;
    while (lo + 1 < hi) { int m = (lo + hi) >> 1; if (g_tile_off[m] <= tile) lo = m; else hi = m; }
    const int e = lo;
    const int p0 = g_off[e] + (tile - g_tile_off[e]) * TMTOK;

    if (tid < TMTOK) {
        int tk = g_perm[p0 + tid];
        s_tok[tid] = tk;
        s_w[tid] = (tk >= 0) ? g_pw[p0 + tid] : 0.f;
    }
    __syncthreads();

    const uint32_t bufs[3] = { sb, sb + STAGE, sb + 2 * STAGE };
    const int rbase = wm * 32 + (lane >> 2);

    // ================= GEMM1: h1/h3, 8 I-chunks of 64, K=32 x 32 =================
    for (int ic = 0; ic < 8; ic++) {
        ld_g1(bufs[0], s_tok, e, ic, 0); CP_COMMIT();
        ld_g1(bufs[1], s_tok, e, ic, 1); CP_COMMIT();
        float c1[2][2][4], c3[2][2][4];
#pragma unroll
        for (int a = 0; a < 2; a++)
#pragma unroll
            for (int b = 0; b < 2; b++)
#pragma unroll
                for (int c = 0; c < 4; c++) { c1[a][b][c] = 0.f; c3[a][b][c] = 0.f; }

        for (int k = 0; k < 32; k++) {
            if (k < 31) CP_WAIT(1); else CP_WAIT(0);
            __syncthreads();
            if (k + 2 < 32) { ld_g1(bufs[(k + 2) % 3], s_tok, e, ic, k + 2); CP_COMMIT(); }
            uint32_t cb = bufs[k % 3];
#pragma unroll
            for (int ks = 0; ks < 2; ks++) {
                uint32_t ah[2][4], al[2][4];
#pragma unroll
                for (int mi = 0; mi < 2; mi++) {
                    ldm4(ah[mi], adr(cb, wm * 32 + mi * 16, ks, lane));
                    ldm4(al[mi], adr(cb, 128 + wm * 32 + mi * 16, ks, lane));
                }
                uint32_t b1h[4], b1l[4], b3h[4], b3l[4];
                ldm4(b1h, adr(cb, 256 + wn * 16, ks, lane));
                ldm4(b1l, adr(cb, 320 + wn * 16, ks, lane));
                ldm4(b3h, adr(cb, 384 + wn * 16, ks, lane));
                ldm4(b3l, adr(cb, 448 + wn * 16, ks, lane));
#pragma unroll
                for (int nk = 0; nk < 2; nk++)
#pragma unroll
                    for (int mi = 0; mi < 2; mi++) {
                        mma16(c1[mi][nk], ah[mi], b1h[nk], b1h[nk + 2]);
                        mma16(c1[mi][nk], al[mi], b1h[nk], b1h[nk + 2]);
                        mma16(c1[mi][nk], ah[mi], b1l[nk], b1l[nk + 2]);
                        mma16(c3[mi][nk], ah[mi], b3h[nk], b3h[nk + 2]);
                        mma16(c3[mi][nk], al[mi], b3h[nk], b3h[nk + 2]);
                        mma16(c3[mi][nk], ah[mi], b3l[nk], b3l[nk + 2]);
                    }
            }
        }
        // epilogue: silu(h1)*h3*w -> bf16 hi/lo scratch
#pragma unroll
        for (int mi = 0; mi < 2; mi++)
#pragma unroll
            for (int nk = 0; nk < 2; nk++)
#pragma unroll
                for (int hf = 0; hf < 2; hf++) {
                    int row = rbase + mi * 16 + hf * 8;
                    int col = ic * 64 + wn * 16 + nk * 8 + ((lane & 3) << 1);
                    float w = s_w[row];
                    float h1a = c1[mi][nk][hf * 2], h1b = c1[mi][nk][hf * 2 + 1];
                    float a0 = h1a / (1.f + __expf(-h1a)) * c3[mi][nk][hf * 2] * w;
                    float a1 = h1b / (1.f + __expf(-h1b)) * c3[mi][nk][hf * 2 + 1] * w;
                    uint32_t hv, lv; split2(a0, a1, hv, lv);
                    size_t o = ((size_t)(tile * TMTOK + row) * IDIM + col) >> 1;
                    g_ahi32[o] = hv; g_alo32[o] = lv;
                }
        __syncthreads();
    }
    __threadfence();
    __syncthreads();

    // ================= GEMM2: y = a @ W2^T, 16 H-chunks of 64, K=16 x 32 =================
    for (int hc = 0; hc < 16; hc++) {
        ld_g2(bufs[0], tile, e, hc, 0); CP_COMMIT();
        ld_g2(bufs[1], tile, e, hc, 1); CP_COMMIT();
        float cc[2][2][4];
#pragma unroll
        for (int a = 0; a < 2; a++)
#pragma unroll
            for (int b = 0; b < 2; b++)
#pragma unroll
                for (int c = 0; c < 4; c++) cc[a][b][c] = 0.f;

        for (int k = 0; k < 16; k++) {
            if (k < 15) CP_WAIT(1); else CP_WAIT(0);
            __syncthreads();
            if (k + 2 < 16) { ld_g2(bufs[(k + 2) % 3], tile, e, hc, k + 2); CP_COMMIT(); }
            uint32_t cb = bufs[k % 3];
#pragma unroll
            for (int ks = 0; ks < 2; ks++) {
                uint32_t ah[2][4], al[2][4];
#pragma unroll
                for (int mi = 0; mi < 2; mi++) {
                    ldm4(ah[mi], adr(cb, wm * 32 + mi * 16, ks, lane));
                    ldm4(al[mi], adr(cb, 128 + wm * 32 + mi * 16, ks, lane));
                }
                uint32_t b2h[4], b2l[4];
                ldm4(b2h, adr(cb, 256 + wn * 16, ks, lane));
                ldm4(b2l, adr(cb, 320 + wn * 16, ks, lane));
#pragma unroll
                for (int nk = 0; nk < 2; nk++)
#pragma unroll
                    for (int mi = 0; mi < 2; mi++) {
                        mma16(cc[mi][nk], ah[mi], b2h[nk], b2h[nk + 2]);
                        mma16(cc[mi][nk], al[mi], b2h[nk], b2h[nk + 2]);
                        mma16(cc[mi][nk], ah[mi], b2l[nk], b2l[nk + 2]);
                    }
            }
        }
#pragma unroll
        for (int mi = 0; mi < 2; mi++)
#pragma unroll
            for (int nk = 0; nk < 2; nk++)
#pragma unroll
                for (int hf = 0; hf < 2; hf++) {
                    int row = rbase + mi * 16 + hf * 8;
                    int col = hc * 64 + wn * 16 + nk * 8 + ((lane & 3) << 1);
                    float2 v = make_float2(cc[mi][nk][hf * 2], cc[mi][nk][hf * 2 + 1]);
                    *(float2*)&g_y[(size_t)(tile * TMTOK + row) * H + col] = v;
                }
        __syncthreads();
    }
}

// ---------------- gather ----------------
__global__ void k_gather(float* __restrict__ out) {
    int idx = blockIdx.x * 256 + threadIdx.x;
    if (idx >= T * H / 4) return;
    int t = idx / (H / 4), c = idx % (H / 4);
    int p0 = g_ypos[2 * t], p1 = g_ypos[2 * t + 1];
    float4 a = ((const float4*)g_y)[(size_t)p0 * (H / 4) + c];
    float4 b = ((const float4*)g_y)[(size_t)p1 * (H / 4) + c];
    ((float4*)out)[idx] = make_float4(a.x + b.x, a.y + b.y, a.z + b.z, a.w + b.w);
}

// ---------------- launch ----------------
extern "C" void kernel_launch(void* const* d_in, const int* in_sizes, int n_in,
                              void* d_out, int out_size) {
    const float* x  = (const float*)d_in[0];
    const float* gw = (const float*)d_in[1];
    const float* gb = (const float*)d_in[2];
    const float* W1 = (const float*)d_in[3];
    const float* W2 = (const float*)d_in[4];
    const float* W3 = (const float*)d_in[5];
    float* out = (float*)d_out;

    cudaFuncSetAttribute(k_router, cudaFuncAttributeMaxDynamicSharedMemorySize, 86016);
    cudaFuncSetAttribute(k_ffn,    cudaFuncAttributeMaxDynamicSharedMemorySize, SMEM_REQ);

    k_cvt<<<2048, 256>>>(x, W1, W2, W3);
    k_router<<<T / 16, 256, 86016>>>(x, gw, gb);
    k_aux<<<1, 256>>>();
    k_ffn<<<NTILES, 512, SMEM_REQ>>>();
    k_gather<<<(T * H / 4 + 255) / 256, 256>>>(out);
}

// round 6
// speedup vs baseline: 1.3693x; 1.0039x over previous
#include <cuda_runtime.h>
#include <math.h>
#include <stdint.h>

#define T      4096
#define H      1024
#define IDIM   512
#define E      64
#define TOPK   2
#define TMTOK  128
#define NTILES 128
#define PPOS   (T*TOPK + E*TMTOK)

// ---------------- device scratch ----------------
__device__ int   g_off[E+1];
__device__ int   g_tile_off[E+1];
__device__ int   g_perm[PPOS];
__device__ float g_pw[PPOS];
__device__ int   g_sel[T*TOPK];
__device__ float g_w[T*TOPK];
__device__ int   g_ypos[T*TOPK];
__device__ uint2 g_xhi[(T+1)*H/4],   g_xlo[(T+1)*H/4];
__device__ uint2 g_w1hi[E*IDIM*H/4], g_w1lo[E*IDIM*H/4];
__device__ uint2 g_w3hi[E*IDIM*H/4], g_w3lo[E*IDIM*H/4];
__device__ uint2 g_w2hi[E*H*IDIM/4], g_w2lo[E*H*IDIM/4];
__device__ uint32_t g_ahi32[NTILES*TMTOK*IDIM/2], g_alo32[NTILES*TMTOK*IDIM/2];
__device__ float g_y[(size_t)NTILES*TMTOK*H];

// ---------------- helpers ----------------
__device__ __forceinline__ uint32_t smem_u32(const void* p) {
    uint32_t a;
    asm("{ .reg .u64 t; cvta.to.shared.u64 t, %1; cvt.u32.u64 %0, t; }" : "=r"(a) : "l"(p));
    return a;
}
__device__ __forceinline__ void cpa16(uint32_t dst, const void* src) {
    asm volatile("cp.async.cg.shared.global [%0], [%1], 16;" :: "r"(dst), "l"(src) : "memory");
}
#define CP_COMMIT() asm volatile("cp.async.commit_group;" ::: "memory")
#define CP_WAIT(n)  asm volatile("cp.async.wait_group %0;" :: "n"(n) : "memory")

__device__ __forceinline__ void ldm4(uint32_t* r, uint32_t addr) {
    asm volatile("ldmatrix.sync.aligned.m8n8.x4.shared.b16 {%0,%1,%2,%3}, [%4];"
        : "=r"(r[0]), "=r"(r[1]), "=r"(r[2]), "=r"(r[3]) : "r"(addr));
}
__device__ __forceinline__ void mma16(float* d, const uint32_t* a, uint32_t b0, uint32_t b1) {
    asm volatile("mma.sync.aligned.m16n8k16.row.col.f32.bf16.bf16.f32 "
        "{%0,%1,%2,%3}, {%4,%5,%6,%7}, {%8,%9}, {%0,%1,%2,%3};"
        : "+f"(d[0]), "+f"(d[1]), "+f"(d[2]), "+f"(d[3])
        : "r"(a[0]), "r"(a[1]), "r"(a[2]), "r"(a[3]), "r"(b0), "r"(b1));
}
__device__ __forceinline__ void split2(float a, float b, uint32_t& hi, uint32_t& lo) {
    uint32_t h;
    asm("cvt.rn.bf16x2.f32 %0, %1, %2;" : "=r"(h) : "f"(b), "f"(a));
    float ra = a - __uint_as_float(h << 16);
    float rb = b - __uint_as_float(h & 0xffff0000u);
    asm("cvt.rn.bf16x2.f32 %0, %1, %2;" : "=r"(lo) : "f"(rb), "f"(ra));
    hi = h;
}

// ---------------- convert fp32 -> bf16 hi/lo ----------------
#define X4   (T*H/4)
#define W14  (E*IDIM*H/4)
#define TOT4 (X4 + 3*W14)
__global__ void k_cvt(const float* __restrict__ x, const float* __restrict__ W1,
                      const float* __restrict__ W2, const float* __restrict__ W3) {
    size_t gid = (size_t)blockIdx.x * blockDim.x + threadIdx.x;
    size_t stride = (size_t)gridDim.x * blockDim.x;
    if (gid < H/4) { g_xhi[(size_t)T*H/4 + gid] = make_uint2(0,0); g_xlo[(size_t)T*H/4 + gid] = make_uint2(0,0); }
    for (size_t i = gid; i < TOT4; i += stride) {
        const float4* s; uint2 *dh, *dl; size_t j = i;
        if (j < X4)            { s = (const float4*)x;  dh = g_xhi;  dl = g_xlo; }
        else { j -= X4;
            if (j < W14)       { s = (const float4*)W1; dh = g_w1hi; dl = g_w1lo; }
            else { j -= W14;
                if (j < W14)   { s = (const float4*)W3; dh = g_w3hi; dl = g_w3lo; }
                else { j -= W14; s = (const float4*)W2; dh = g_w2hi; dl = g_w2lo; } } }
        float4 v = s[j];
        uint32_t h0,l0,h1,l1;
        split2(v.x, v.y, h0, l0);
        split2(v.z, v.w, h1, l1);
        dh[j] = make_uint2(h0, h1);
        dl[j] = make_uint2(l0, l1);
    }
}

// ---------------- router (16 tokens / block) ----------------
__global__ void __launch_bounds__(256) k_router(const float* __restrict__ x,
                                                const float* __restrict__ gw,
                                                const float* __restrict__ gb) {
    extern __shared__ float rsm[];
    float* xs  = rsm;
    float* red = rsm + 16384;
    float* lg  = red + 4096;
    const int t0 = blockIdx.x * 16;
    const int tid = threadIdx.x;
    float4* xs4 = (float4*)xs;
    const float4* xg = (const float4*)(x + (size_t)t0 * H);
    for (int i = tid; i < 16 * H / 4; i += 256) xs4[i] = xg[i];
    __syncthreads();
    const int e = tid & 63, ck = tid >> 6;
    const float4* gwp = (const float4*)(gw + (size_t)e * H + ck * 256);
    float acc[16];
#pragma unroll
    for (int r = 0; r < 16; r++) acc[r] = 0.f;
    for (int j = 0; j < 64; j++) {
        float4 wv = gwp[j];
#pragma unroll
        for (int r = 0; r < 16; r++) {
            float4 xv = xs4[r * 256 + ck * 64 + j];
            acc[r] += xv.x * wv.x + xv.y * wv.y + xv.z * wv.z + xv.w * wv.w;
        }
    }
#pragma unroll
    for (int r = 0; r < 16; r++) red[tid * 16 + r] = acc[r];
    __syncthreads();
    if (tid < 64) {
#pragma unroll
        for (int r = 0; r < 16; r++)
            lg[r * 64 + tid] = red[tid * 16 + r] + red[(tid + 64) * 16 + r] +
                               red[(tid + 128) * 16 + r] + red[(tid + 192) * 16 + r] + gb[tid];
    }
    __syncthreads();
    if (tid < 16) {
        int t = t0 + tid;
        float l0 = -1e30f, l1 = -1e30f;
        int e0 = 0, e1 = 0;
        for (int k = 0; k < E; k++) {
            float l = lg[tid * 64 + k];
            if (l > l0)      { l1 = l0; e1 = e0; l0 = l; e0 = k; }
            else if (l > l1) { l1 = l;  e1 = k; }
        }
        float rr = expf(l1 - l0);
        float w0 = 1.f / (1.f + rr);
        float w1 = rr * w0;
        g_sel[2 * t] = e0;  g_sel[2 * t + 1] = e1;
        g_w[2 * t]   = w0;  g_w[2 * t + 1]   = w1;
    }
}

// ---------------- aux: histogram + scan + pad + scatter ----------------
__global__ void __launch_bounds__(256) k_aux() {
    __shared__ int hist[E];
    __shared__ int soff[E+1], stoff[E+1];
    __shared__ int cur[E];
    const int tid = threadIdx.x;
    if (tid < E) hist[tid] = 0;
    __syncthreads();
    for (int i = tid; i < T * TOPK; i += 256) atomicAdd(&hist[g_sel[i]], 1);
    __syncthreads();
    if (tid == 0) {
        int off = 0, toff = 0;
        for (int e = 0; e < E; e++) {
            soff[e] = off; stoff[e] = toff;
            int tiles = (hist[e] + TMTOK - 1) / TMTOK;
            off += tiles * TMTOK; toff += tiles;
        }
        soff[E] = off; stoff[E] = toff;
    }
    __syncthreads();
    if (tid < E) { cur[tid] = soff[tid]; g_off[tid] = soff[tid]; g_tile_off[tid] = stoff[tid]; }
    if (tid == 0) { g_off[E] = soff[E]; g_tile_off[E] = stoff[E]; }
    for (int i = tid; i < PPOS; i += 256) g_perm[i] = -1;
    __syncthreads();
    for (int i = tid; i < T * TOPK; i += 256) {
        int e = g_sel[i];
        int pos = atomicAdd(&cur[e], 1);
        g_perm[pos] = i >> 1;
        g_pw[pos] = g_w[i];
        int local = pos - soff[e];
        g_ypos[i] = (stoff[e] + (local >> 7)) * TMTOK + (local & 127);
    }
}

// ---------------- FFN: KC=64 stages, term-major MMA ordering ----------------
#define KC      64
#define RSTRIDE 144
#define STAGE   (512*RSTRIDE)
#define SMEM_REQ (3*STAGE)

__device__ __forceinline__ uint32_t adr(uint32_t buf, int rowbase, int ks, int lane) {
    return buf + (uint32_t)(rowbase + (lane & 15)) * RSTRIDE + (uint32_t)(ks * 2 + (lane >> 4)) * 16;
}

// one stage = 512 rows x 128B. rows: [0,128)xhi [128,256)xlo [256,320)w1h [320,384)w1l [384,448)w3h [448,512)w3l
__device__ __forceinline__ void ld_g1(uint32_t buf, const int* s_tok, int e, int ic, int k) {
    const int row = threadIdx.x;
    const char* src;
    if (row < 256) {
        int tok = s_tok[row & 127];
        if (tok < 0) tok = T;
        const char* base = (row < 128) ? (const char*)g_xhi : (const char*)g_xlo;
        src = base + (size_t)tok * (H * 2) + k * (KC * 2);
    } else {
        int n = row & 63;
        int sel = (row - 256) >> 6;
        const char* base = (sel == 0) ? (const char*)g_w1hi :
                           (sel == 1) ? (const char*)g_w1lo :
                           (sel == 2) ? (const char*)g_w3hi : (const char*)g_w3lo;
        src = base + ((size_t)(e * IDIM + ic * 64 + n)) * (H * 2) + k * (KC * 2);
    }
    uint32_t d = buf + (uint32_t)row * RSTRIDE;
#pragma unroll
    for (int q = 0; q < 8; q++) cpa16(d + q * 16, src + q * 16);
}
// rows: [0,128)ahi [128,256)alo [256,320)w2h [320,384)w2l
__device__ __forceinline__ void ld_g2(uint32_t buf, int tile, int e, int hc, int k) {
    const int row = threadIdx.x;
    if (row >= 384) return;
    const char* src;
    if (row < 256) {
        const char* base = (row < 128) ? (const char*)g_ahi32 : (const char*)g_alo32;
        src = base + ((size_t)tile * TMTOK + (row & 127)) * (IDIM * 2) + k * (KC * 2);
    } else {
        int n = row & 63;
        const char* base = (row < 320) ? (const char*)g_w2hi : (const char*)g_w2lo;
        src = base + ((size_t)(e * H + hc * 64 + n)) * (IDIM * 2) + k * (KC * 2);
    }
    uint32_t d = buf + (uint32_t)row * RSTRIDE;
#pragma unroll
    for (int q = 0; q < 8; q++) cpa16(d + q * 16, src + q * 16);
}

__global__ void __launch_bounds__(512, 1) k_ffn() {
    const int tile = blockIdx.x;
    if (tile >= g_tile_off[E]) return;
    extern __shared__ char sm[];
    const uint32_t sb = smem_u32(sm);
    __shared__ int   s_tok[TMTOK];
    __shared__ float s_w[TMTOK];

    const int tid = threadIdx.x, lane = tid & 31, wid = tid >> 5;
    const int wm = wid & 3, wn = wid >> 2;     // 4x4 warp grid: M32 x N16 per warp

    int lo = 0, hi = E;
    while (lo + 1 < hi) { int m = (lo + hi) >> 1; if (g_tile_off[m] <= tile) lo = m; else hi = m; }
    const int e = lo;
    const int p0 = g_off[e] + (tile - g_tile_off[e]) * TMTOK;

    if (tid < TMTOK) {
        int tk = g_perm[p0 + tid];
        s_tok[tid] = tk;
        s_w[tid] = (tk >= 0) ? g_pw[p0 + tid] : 0.f;
    }
    __syncthreads();

    const uint32_t bufs[3] = { sb, sb + STAGE, sb + 2 * STAGE };
    const int rbase = wm * 32 + (lane >> 2);

    // ================= GEMM1: h1/h3, 8 I-chunks of 64, K = 16 x KC64 =================
    for (int ic = 0; ic < 8; ic++) {
        ld_g1(bufs[0], s_tok, e, ic, 0); CP_COMMIT();
        ld_g1(bufs[1], s_tok, e, ic, 1); CP_COMMIT();
        float c1[2][2][4], c3[2][2][4];
#pragma unroll
        for (int a = 0; a < 2; a++)
#pragma unroll
            for (int b = 0; b < 2; b++)
#pragma unroll
                for (int c = 0; c < 4; c++) { c1[a][b][c] = 0.f; c3[a][b][c] = 0.f; }

        for (int k = 0; k < 16; k++) {
            if (k < 15) CP_WAIT(1); else CP_WAIT(0);
            __syncthreads();
            if (k + 2 < 16) { ld_g1(bufs[(k + 2) % 3], s_tok, e, ic, k + 2); CP_COMMIT(); }
            uint32_t cb = bufs[k % 3];
#pragma unroll
            for (int ks = 0; ks < 4; ks++) {
                uint32_t ah[2][4], al[2][4];
                ldm4(ah[0], adr(cb, wm * 32,            ks, lane));
                ldm4(ah[1], adr(cb, wm * 32 + 16,       ks, lane));
                ldm4(al[0], adr(cb, 128 + wm * 32,      ks, lane));
                ldm4(al[1], adr(cb, 128 + wm * 32 + 16, ks, lane));
                uint32_t b1h[4], b1l[4], b3h[4], b3l[4];
                ldm4(b1h, adr(cb, 256 + wn * 16, ks, lane));
                ldm4(b1l, adr(cb, 320 + wn * 16, ks, lane));
                ldm4(b3h, adr(cb, 384 + wn * 16, ks, lane));
                ldm4(b3l, adr(cb, 448 + wn * 16, ks, lane));
                // term 0: hi*hi (8 independent MMAs)
#pragma unroll
                for (int nk = 0; nk < 2; nk++)
#pragma unroll
                    for (int mi = 0; mi < 2; mi++) mma16(c1[mi][nk], ah[mi], b1h[nk], b1h[nk + 2]);
#pragma unroll
                for (int nk = 0; nk < 2; nk++)
#pragma unroll
                    for (int mi = 0; mi < 2; mi++) mma16(c3[mi][nk], ah[mi], b3h[nk], b3h[nk + 2]);
                // term 1: lo*hi
#pragma unroll
                for (int nk = 0; nk < 2; nk++)
#pragma unroll
                    for (int mi = 0; mi < 2; mi++) mma16(c1[mi][nk], al[mi], b1h[nk], b1h[nk + 2]);
#pragma unroll
                for (int nk = 0; nk < 2; nk++)
#pragma unroll
                    for (int mi = 0; mi < 2; mi++) mma16(c3[mi][nk], al[mi], b3h[nk], b3h[nk + 2]);
                // term 2: hi*lo
#pragma unroll
                for (int nk = 0; nk < 2; nk++)
#pragma unroll
                    for (int mi = 0; mi < 2; mi++) mma16(c1[mi][nk], ah[mi], b1l[nk], b1l[nk + 2]);
#pragma unroll
                for (int nk = 0; nk < 2; nk++)
#pragma unroll
                    for (int mi = 0; mi < 2; mi++) mma16(c3[mi][nk], ah[mi], b3l[nk], b3l[nk + 2]);
            }
        }
        // epilogue: silu(h1)*h3*w -> bf16 hi/lo scratch
#pragma unroll
        for (int mi = 0; mi < 2; mi++)
#pragma unroll
            for (int nk = 0; nk < 2; nk++)
#pragma unroll
                for (int hf = 0; hf < 2; hf++) {
                    int row = rbase + mi * 16 + hf * 8;
                    int col = ic * 64 + wn * 16 + nk * 8 + ((lane & 3) << 1);
                    float w = s_w[row];
                    float h1a = c1[mi][nk][hf * 2], h1b = c1[mi][nk][hf * 2 + 1];
                    float a0 = h1a / (1.f + __expf(-h1a)) * c3[mi][nk][hf * 2] * w;
                    float a1 = h1b / (1.f + __expf(-h1b)) * c3[mi][nk][hf * 2 + 1] * w;
                    uint32_t hv, lv; split2(a0, a1, hv, lv);
                    size_t o = ((size_t)(tile * TMTOK + row) * IDIM + col) >> 1;
                    g_ahi32[o] = hv; g_alo32[o] = lv;
                }
        __syncthreads();
    }
    __threadfence();
    __syncthreads();

    // ================= GEMM2: y = a @ W2^T, 16 H-chunks of 64, K = 8 x KC64 =================
    for (int hc = 0; hc < 16; hc++) {
        ld_g2(bufs[0], tile, e, hc, 0); CP_COMMIT();
        ld_g2(bufs[1], tile, e, hc, 1); CP_COMMIT();
        float cc[2][2][4];
#pragma unroll
        for (int a = 0; a < 2; a++)
#pragma unroll
            for (int b = 0; b < 2; b++)
#pragma unroll
                for (int c = 0; c < 4; c++) cc[a][b][c] = 0.f;

        for (int k = 0; k < 8; k++) {
            if (k < 7) CP_WAIT(1); else CP_WAIT(0);
            __syncthreads();
            if (k + 2 < 8) { ld_g2(bufs[(k + 2) % 3], tile, e, hc, k + 2); CP_COMMIT(); }
            uint32_t cb = bufs[k % 3];
#pragma unroll
            for (int ks = 0; ks < 4; ks++) {
                uint32_t ah[2][4], al[2][4];
                ldm4(ah[0], adr(cb, wm * 32,            ks, lane));
                ldm4(ah[1], adr(cb, wm * 32 + 16,       ks, lane));
                ldm4(al[0], adr(cb, 128 + wm * 32,      ks, lane));
                ldm4(al[1], adr(cb, 128 + wm * 32 + 16, ks, lane));
                uint32_t b2h[4], b2l[4];
                ldm4(b2h, adr(cb, 256 + wn * 16, ks, lane));
                ldm4(b2l, adr(cb, 320 + wn * 16, ks, lane));
                // term 0
#pragma unroll
                for (int nk = 0; nk < 2; nk++)
#pragma unroll
                    for (int mi = 0; mi < 2; mi++) mma16(cc[mi][nk], ah[mi], b2h[nk], b2h[nk + 2]);
                // term 1
#pragma unroll
                for (int nk = 0; nk < 2; nk++)
#pragma unroll
                    for (int mi = 0; mi < 2; mi++) mma16(cc[mi][nk], al[mi], b2h[nk], b2h[nk + 2]);
                // term 2
#pragma unroll
                for (int nk = 0; nk < 2; nk++)
#pragma unroll
                    for (int mi = 0; mi < 2; mi++) mma16(cc[mi][nk], ah[mi], b2l[nk], b2l[nk + 2]);
            }
        }
#pragma unroll
        for (int mi = 0; mi < 2; mi++)
#pragma unroll
            for (int nk = 0; nk < 2; nk++)
#pragma unroll
                for (int hf = 0; hf < 2; hf++) {
                    int row = rbase + mi * 16 + hf * 8;
                    int col = hc * 64 + wn * 16 + nk * 8 + ((lane & 3) << 1);
                    float2 v = make_float2(cc[mi][nk][hf * 2], cc[mi][nk][hf * 2 + 1]);
                    *(float2*)&g_y[(size_t)(tile * TMTOK + row) * H + col] = v;
                }
        __syncthreads();
    }
}

// ---------------- gather ----------------
__global__ void k_gather(float* __restrict__ out) {
    int idx = blockIdx.x * 256 + threadIdx.x;
    if (idx >= T * H / 4) return;
    int t = idx / (H / 4), c = idx % (H / 4);
    int p0 = g_ypos[2 * t], p1 = g_ypos[2 * t + 1];
    float4 a = ((const float4*)g_y)[(size_t)p0 * (H / 4) + c];
    float4 b = ((const float4*)g_y)[(size_t)p1 * (H / 4) + c];
    ((float4*)out)[idx] = make_float4(a.x + b.x, a.y + b.y, a.z + b.z, a.w + b.w);
}

// ---------------- launch ----------------
extern "C" void kernel_launch(void* const* d_in, const int* in_sizes, int n_in,
                              void* d_out, int out_size) {
    const float* x  = (const float*)d_in[0];
    const float* gw = (const float*)d_in[1];
    const float* gb = (const float*)d_in[2];
    const float* W1 = (const float*)d_in[3];
    const float* W2 = (const float*)d_in[4];
    const float* W3 = (const float*)d_in[5];
    float* out = (float*)d_out;

    cudaFuncSetAttribute(k_router, cudaFuncAttributeMaxDynamicSharedMemorySize, 86016);
    cudaFuncSetAttribute(k_ffn,    cudaFuncAttributeMaxDynamicSharedMemorySize, SMEM_REQ);

    k_cvt<<<2048, 256>>>(x, W1, W2, W3);
    k_router<<<T / 16, 256, 86016>>>(x, gw, gb);
    k_aux<<<1, 256>>>();
    k_ffn<<<NTILES, 512, SMEM_REQ>>>();
    k_gather<<<(T * H / 4 + 255) / 256, 256>>>(out);
}